// round 2
// baseline (speedup 1.0000x reference)
#include <cuda_runtime.h>
#include <cstdint>

#define B_   2
#define S_   2048
#define HID_ 4096
#define NH_  32
#define NKV_ 8
#define HD_  128

// ---------------- device scratch (no cudaMalloc allowed) ----------------
__device__ float g_q[(size_t)B_ * NH_ * S_ * HD_];    // [B,NH,S,HD]
__device__ float g_k[(size_t)B_ * NKV_ * S_ * HD_];   // [B,NKV,S,HD]
__device__ float g_v[(size_t)B_ * NKV_ * S_ * HD_];   // [B,NKV,S,HD]
__device__ float g_ctx[(size_t)B_ * S_ * HID_];       // [B,S,HID]

// ---------------- helpers ----------------
__device__ __forceinline__ void cp16(void* dst, const void* src) {
    unsigned d = (unsigned)__cvta_generic_to_shared(dst);
    asm volatile("cp.async.cg.shared.global [%0], [%1], 16;\n" :: "r"(d), "l"(src));
}
__device__ __forceinline__ void cp_commit() { asm volatile("cp.async.commit_group;\n"); }
__device__ __forceinline__ void cp_wait0()  { asm volatile("cp.async.wait_group 0;\n"); }

// m16n8k8 tf32 mma
__device__ __forceinline__ void mma8(float& c0, float& c1, float& c2, float& c3,
                                     uint32_t a0, uint32_t a1, uint32_t a2, uint32_t a3,
                                     uint32_t b0, uint32_t b1) {
    asm volatile(
        "mma.sync.aligned.m16n8k8.row.col.f32.tf32.tf32.f32 "
        "{%0,%1,%2,%3},{%4,%5,%6,%7},{%8,%9},{%0,%1,%2,%3};\n"
        : "+f"(c0), "+f"(c1), "+f"(c2), "+f"(c3)
        : "r"(a0), "r"(a1), "r"(a2), "r"(a3), "r"(b0), "r"(b1));
}

// split fp32 into tf32 hi + residual lo (tf32x3 trick)
__device__ __forceinline__ void split_tf32(float x, uint32_t& hi, uint32_t& lo) {
    uint32_t h;
    asm("cvt.rna.tf32.f32 %0, %1;\n" : "=r"(h) : "f"(x));
    hi = h;
    lo = __float_as_uint(x - __uint_as_float(h));
}

// 3-product mma: acc += a*b in ~fp32 precision
__device__ __forceinline__ void mma8_x3(float* c,
    const uint32_t* ah, const uint32_t* al,
    uint32_t bh0, uint32_t bh1, uint32_t bl0, uint32_t bl1) {
    mma8(c[0], c[1], c[2], c[3], ah[0], ah[1], ah[2], ah[3], bh0, bh1);
    mma8(c[0], c[1], c[2], c[3], al[0], al[1], al[2], al[3], bh0, bh1);
    mma8(c[0], c[1], c[2], c[3], ah[0], ah[1], ah[2], ah[3], bl0, bl1);
}

// ---------------- NT GEMM: C[m,n] = sum_k A[m,k] * W[n,k]  (tf32x3) ----------------
#define GBM 128
#define GBN 256
#define GBK 16
#define GPAD 20

__global__ __launch_bounds__(256, 1) void gemm_nt(
    const float* __restrict__ A, const float* __restrict__ W0, const float* __restrict__ W1,
    const float* __restrict__ bias, float* __restrict__ C,
    int M, int N, int K, int nsplit, int mode)
{
    extern __shared__ float sm[];
    float* As = sm;                   // [2][128][GPAD]
    float* Bs = sm + 2 * GBM * GPAD;  // [2][256][GPAD]

    int tid = threadIdx.x;
    int lane = tid & 31, wid = tid >> 5;
    int g = lane >> 2, tg = lane & 3;
    int wm = (wid & 1) << 6;
    int wn = (wid >> 1) << 6;

    int m0 = blockIdx.y * GBM;
    int n0 = blockIdx.x * GBN;
    const float* Bw = (n0 >= nsplit) ? (W1 + (size_t)(n0 - nsplit) * K)
                                     : (W0 + (size_t)n0 * K);
    const float* Ab = A + (size_t)m0 * K;

    float acc[4][8][4];
#pragma unroll
    for (int i = 0; i < 4; i++)
#pragma unroll
        for (int j = 0; j < 8; j++)
#pragma unroll
            for (int c = 0; c < 4; c++) acc[i][j][c] = 0.f;

    int nk = K / GBK;

    auto load_tile = [&](int kt, int buf) {
        int k0 = kt * GBK;
        float* as = As + buf * GBM * GPAD;
        float* bs = Bs + buf * GBN * GPAD;
#pragma unroll
        for (int i = 0; i < 2; i++) {
            int idx = tid + i * 256;
            int row = idx >> 2, q = idx & 3;
            cp16(&as[row * GPAD + q * 4], Ab + (size_t)row * K + k0 + q * 4);
        }
#pragma unroll
        for (int i = 0; i < 4; i++) {
            int idx = tid + i * 256;
            int row = idx >> 2, q = idx & 3;
            cp16(&bs[row * GPAD + q * 4], Bw + (size_t)row * K + k0 + q * 4);
        }
    };

    load_tile(0, 0);
    cp_commit();

    for (int kt = 0; kt < nk; kt++) {
        cp_wait0();
        __syncthreads();
        int buf = kt & 1;
        if (kt + 1 < nk) { load_tile(kt + 1, buf ^ 1); cp_commit(); }

        const float* as = As + buf * GBM * GPAD;
        const float* bs = Bs + buf * GBN * GPAD;
#pragma unroll
        for (int k8 = 0; k8 < 2; k8++) {
            int kk = k8 * 8;
            uint32_t afh[4][4], afl[4][4];
#pragma unroll
            for (int mi = 0; mi < 4; mi++) {
                int r = wm + mi * 16 + g;
                split_tf32(as[r * GPAD + kk + tg],           afh[mi][0], afl[mi][0]);
                split_tf32(as[(r + 8) * GPAD + kk + tg],     afh[mi][1], afl[mi][1]);
                split_tf32(as[r * GPAD + kk + tg + 4],       afh[mi][2], afl[mi][2]);
                split_tf32(as[(r + 8) * GPAD + kk + tg + 4], afh[mi][3], afl[mi][3]);
            }
#pragma unroll
            for (int nj = 0; nj < 8; nj++) {
                int c = wn + nj * 8 + g;
                uint32_t bh0, bh1, bl0, bl1;
                split_tf32(bs[c * GPAD + kk + tg],     bh0, bl0);
                split_tf32(bs[c * GPAD + kk + tg + 4], bh1, bl1);
#pragma unroll
                for (int mi = 0; mi < 4; mi++)
                    mma8_x3(acc[mi][nj], afh[mi], afl[mi], bh0, bh1, bl0, bl1);
            }
        }
    }

    // epilogue
#pragma unroll
    for (int mi = 0; mi < 4; mi++) {
#pragma unroll
        for (int nj = 0; nj < 8; nj++) {
#pragma unroll
            for (int c = 0; c < 4; c++) {
                int row = m0 + wm + mi * 16 + g + ((c & 2) ? 8 : 0);
                int col = n0 + wn + nj * 8 + tg * 2 + (c & 1);
                float v = acc[mi][nj][c];
                if (mode == 0) {
                    C[(size_t)row * N + col] = v + bias[col];
                } else {
                    int bb = row >> 11, s = row & (S_ - 1);
                    if (col < HID_) {
                        int h = col >> 7, d = col & 127;
                        g_q[(((size_t)bb * NH_ + h) * S_ + s) * HD_ + d] = v;
                    } else {
                        int n2 = col - HID_;
                        int kh = n2 >> 8, cc = n2 & 255;
                        if (cc < 128)
                            g_k[(((size_t)bb * NKV_ + kh) * S_ + s) * HD_ + cc] = v;
                        else
                            g_v[(((size_t)bb * NKV_ + kh) * S_ + s) * HD_ + cc - 128] = v;
                    }
                }
            }
        }
    }
}

// ---------------- RoPE (in-place on g_q, g_k) ----------------
__global__ void rope_kernel(const float* __restrict__ cosT, const float* __restrict__ sinT)
{
    int idx = blockIdx.x * blockDim.x + threadIdx.x;
    int d = idx & 63;
    int r = idx >> 6;
    int s = r & (S_ - 1);
    int hh = r >> 11;
    float c1 = cosT[s * HD_ + d],      s1 = sinT[s * HD_ + d];
    float c2 = cosT[s * HD_ + d + 64], s2 = sinT[s * HD_ + d + 64];
    float* p;
    if (hh < B_ * NH_) p = g_q + (size_t)r * HD_;
    else               p = g_k + (size_t)(r - B_ * NH_ * S_) * HD_;
    float x1 = p[d], x2 = p[d + 64];
    p[d]      = x1 * c1 - x2 * s1;
    p[d + 64] = x2 * c2 + x1 * s2;
}

// ---------------- Flash attention (causal, GQA), tf32x3 ----------------
#define AQ 128
#define AK 64
#define QSL 132
#define KSL 132
#define VSL 136
#define PSL 68

__global__ __launch_bounds__(256, 1) void attn_kernel()
{
    extern __shared__ float sm[];
    float* Qs = sm;               // [128][132]
    float* Ks = Qs + AQ * QSL;    // [64][132]
    float* Vs = Ks + AK * KSL;    // [64][136]
    float* Ps = Vs + AK * VSL;    // [128][68]

    int qt = blockIdx.x, h = blockIdx.y, b = blockIdx.z;
    int tid = threadIdx.x, lane = tid & 31, wid = tid >> 5;
    int g = lane >> 2, tg = lane & 3;

    const float* Qb = g_q + (((size_t)b * NH_ + h) * S_ + (size_t)qt * AQ) * HD_;
    const float* Kb = g_k + (((size_t)b * NKV_ + (h >> 2)) * S_) * HD_;
    const float* Vb = g_v + (((size_t)b * NKV_ + (h >> 2)) * S_) * HD_;

#pragma unroll
    for (int i = 0; i < 16; i++) {
        int idx = tid + i * 256;
        int row = idx >> 5, q = idx & 31;
        cp16(&Qs[row * QSL + q * 4], Qb + (size_t)row * HD_ + q * 4);
    }
    cp_commit();

    float o[16][4];
#pragma unroll
    for (int j = 0; j < 16; j++)
#pragma unroll
        for (int c = 0; c < 4; c++) o[j][c] = 0.f;
    float m0 = -1e30f, m1 = -1e30f, l0 = 0.f, l1 = 0.f;
    const float scale = 0.08838834764831845f;

    int nkt = (qt + 1) * 2;
    for (int kt = 0; kt < nkt; kt++) {
        __syncthreads();
#pragma unroll
        for (int i = 0; i < 8; i++) {
            int idx = tid + i * 256;
            int row = idx >> 5, q = idx & 31;
            cp16(&Ks[row * KSL + q * 4], Kb + (size_t)(kt * AK + row) * HD_ + q * 4);
            cp16(&Vs[row * VSL + q * 4], Vb + (size_t)(kt * AK + row) * HD_ + q * 4);
        }
        cp_commit();
        cp_wait0();
        __syncthreads();

        // S = Q K^T
        float sf[8][4];
#pragma unroll
        for (int j = 0; j < 8; j++)
#pragma unroll
            for (int c = 0; c < 4; c++) sf[j][c] = 0.f;
        int pr = wid * 16 + g;
#pragma unroll
        for (int k8 = 0; k8 < 16; k8++) {
            int kk = k8 * 8;
            uint32_t ah[4], al[4];
            split_tf32(Qs[pr * QSL + kk + tg],           ah[0], al[0]);
            split_tf32(Qs[(pr + 8) * QSL + kk + tg],     ah[1], al[1]);
            split_tf32(Qs[pr * QSL + kk + tg + 4],       ah[2], al[2]);
            split_tf32(Qs[(pr + 8) * QSL + kk + tg + 4], ah[3], al[3]);
#pragma unroll
            for (int nj = 0; nj < 8; nj++) {
                uint32_t bh0, bh1, bl0, bl1;
                split_tf32(Ks[(nj * 8 + g) * KSL + kk + tg],     bh0, bl0);
                split_tf32(Ks[(nj * 8 + g) * KSL + kk + tg + 4], bh1, bl1);
                mma8_x3(sf[nj], ah, al, bh0, bh1, bl0, bl1);
            }
        }

        // scale + causal mask + row max
        int row0 = qt * AQ + wid * 16 + g;
        int colb = kt * AK + tg * 2;
        float mx0 = -1e30f, mx1 = -1e30f;
#pragma unroll
        for (int nj = 0; nj < 8; nj++) {
#pragma unroll
            for (int c = 0; c < 4; c++) {
                int col = colb + nj * 8 + (c & 1);
                int row = row0 + ((c & 2) ? 8 : 0);
                float v = sf[nj][c] * scale;
                if (col > row) v = -1e30f;
                sf[nj][c] = v;
                if (c < 2) mx0 = fmaxf(mx0, v); else mx1 = fmaxf(mx1, v);
            }
        }
        mx0 = fmaxf(mx0, __shfl_xor_sync(0xffffffffu, mx0, 1));
        mx0 = fmaxf(mx0, __shfl_xor_sync(0xffffffffu, mx0, 2));
        mx1 = fmaxf(mx1, __shfl_xor_sync(0xffffffffu, mx1, 1));
        mx1 = fmaxf(mx1, __shfl_xor_sync(0xffffffffu, mx1, 2));

        float mn0 = fmaxf(m0, mx0), mn1 = fmaxf(m1, mx1);
        float al0 = __expf(m0 - mn0), al1 = __expf(m1 - mn1);
        m0 = mn0; m1 = mn1;

        float rs0 = 0.f, rs1 = 0.f;
#pragma unroll
        for (int nj = 0; nj < 8; nj++) {
            float p0 = __expf(sf[nj][0] - mn0), p1 = __expf(sf[nj][1] - mn0);
            float p2 = __expf(sf[nj][2] - mn1), p3 = __expf(sf[nj][3] - mn1);
            sf[nj][0] = p0; sf[nj][1] = p1; sf[nj][2] = p2; sf[nj][3] = p3;
            rs0 += p0 + p1; rs1 += p2 + p3;
        }
        rs0 += __shfl_xor_sync(0xffffffffu, rs0, 1);
        rs0 += __shfl_xor_sync(0xffffffffu, rs0, 2);
        rs1 += __shfl_xor_sync(0xffffffffu, rs1, 1);
        rs1 += __shfl_xor_sync(0xffffffffu, rs1, 2);
        l0 = l0 * al0 + rs0;
        l1 = l1 * al1 + rs1;
#pragma unroll
        for (int j = 0; j < 16; j++) {
            o[j][0] *= al0; o[j][1] *= al0; o[j][2] *= al1; o[j][3] *= al1;
        }

        // stage P through smem (warp-private rows)
#pragma unroll
        for (int nj = 0; nj < 8; nj++) {
            Ps[pr * PSL + nj * 8 + tg * 2]           = sf[nj][0];
            Ps[pr * PSL + nj * 8 + tg * 2 + 1]       = sf[nj][1];
            Ps[(pr + 8) * PSL + nj * 8 + tg * 2]     = sf[nj][2];
            Ps[(pr + 8) * PSL + nj * 8 + tg * 2 + 1] = sf[nj][3];
        }
        __syncwarp();

        // O += P @ V
#pragma unroll
        for (int s8 = 0; s8 < 8; s8++) {
            int ss = s8 * 8;
            uint32_t ah[4], al[4];
            split_tf32(Ps[pr * PSL + ss + tg],           ah[0], al[0]);
            split_tf32(Ps[(pr + 8) * PSL + ss + tg],     ah[1], al[1]);
            split_tf32(Ps[pr * PSL + ss + tg + 4],       ah[2], al[2]);
            split_tf32(Ps[(pr + 8) * PSL + ss + tg + 4], ah[3], al[3]);
#pragma unroll
            for (int dj = 0; dj < 16; dj++) {
                uint32_t bh0, bh1, bl0, bl1;
                split_tf32(Vs[(ss + tg) * VSL + dj * 8 + g],     bh0, bl0);
                split_tf32(Vs[(ss + tg + 4) * VSL + dj * 8 + g], bh1, bl1);
                mma8_x3(o[dj], ah, al, bh0, bh1, bl0, bl1);
            }
        }
    }

    // epilogue
    float il0 = 1.f / l0, il1 = 1.f / l1;
    int row0 = qt * AQ + wid * 16 + g;
    float* cb = g_ctx + ((size_t)b * S_) * HID_ + (size_t)h * HD_;
#pragma unroll
    for (int dj = 0; dj < 16; dj++) {
        int d = dj * 8 + tg * 2;
        cb[(size_t)row0 * HID_ + d]           = o[dj][0] * il0;
        cb[(size_t)row0 * HID_ + d + 1]       = o[dj][1] * il0;
        cb[(size_t)(row0 + 8) * HID_ + d]     = o[dj][2] * il1;
        cb[(size_t)(row0 + 8) * HID_ + d + 1] = o[dj][3] * il1;
    }
}

// ---------------- launch ----------------
extern "C" void kernel_launch(void* const* d_in, const int* in_sizes, int n_in,
                              void* d_out, int out_size)
{
    const float* hs   = (const float*)d_in[0];
    const float* cosT = (const float*)d_in[2];
    const float* sinT = (const float*)d_in[3];
    const float* Wq   = (const float*)d_in[4];
    const float* Wkv  = (const float*)d_in[5];
    const float* Wd   = (const float*)d_in[6];
    const float* bd   = (const float*)d_in[7];
    float* out = (float*)d_out;

    cudaFuncSetAttribute(gemm_nt, cudaFuncAttributeMaxDynamicSharedMemorySize, 61440);
    cudaFuncSetAttribute(attn_kernel, cudaFuncAttributeMaxDynamicSharedMemorySize, 171008);

    void* ctxp = nullptr;
    cudaGetSymbolAddress(&ctxp, g_ctx);

    gemm_nt<<<dim3((HID_ + 2 * NKV_ * HD_) / GBN, (B_ * S_) / GBM), 256, 61440>>>(
        hs, Wq, Wkv, bd, out, B_ * S_, HID_ + 2 * NKV_ * HD_, HID_, HID_, 1);

    rope_kernel<<<(B_ * (NH_ + NKV_) * S_ * 64) / 256, 256>>>(cosT, sinT);

    attn_kernel<<<dim3(S_ / AQ, NH_, B_), 256, 171008>>>();

    gemm_nt<<<dim3(HID_ / GBN, (B_ * S_) / GBM), 256, 61440>>>(
        (const float*)ctxp, Wd, Wd, bd, out, B_ * S_, HID_, HID_, 1 << 30, 0);
}

// round 3
// speedup vs baseline: 1.6907x; 1.6907x over previous
#include <cuda_runtime.h>
#include <cuda_bf16.h>
#include <cstdint>

#define B_   2
#define S_   2048
#define HID_ 4096
#define NH_  32
#define NKV_ 8
#define HD_  128

typedef __nv_bfloat16 bf16;

// ---------------- device scratch (no cudaMalloc allowed) ----------------
__device__ bf16  g_hsh[(size_t)B_ * S_ * HID_];
__device__ bf16  g_hsl[(size_t)B_ * S_ * HID_];
__device__ bf16  g_wh [(size_t)(HID_ + 2 * NKV_ * HD_) * HID_];
__device__ bf16  g_wl [(size_t)(HID_ + 2 * NKV_ * HD_) * HID_];
__device__ bf16  g_wdh[(size_t)HID_ * HID_];
__device__ bf16  g_wdl[(size_t)HID_ * HID_];
__device__ float g_qf [(size_t)B_ * NH_ * S_ * HD_];
__device__ float g_kf [(size_t)B_ * NKV_ * S_ * HD_];
__device__ bf16  g_qh [(size_t)B_ * NH_ * S_ * HD_];
__device__ bf16  g_ql [(size_t)B_ * NH_ * S_ * HD_];
__device__ bf16  g_kh [(size_t)B_ * NKV_ * S_ * HD_];
__device__ bf16  g_kl [(size_t)B_ * NKV_ * S_ * HD_];
__device__ bf16  g_vh [(size_t)B_ * NKV_ * S_ * HD_];
__device__ bf16  g_vl [(size_t)B_ * NKV_ * S_ * HD_];
__device__ bf16  g_ch [(size_t)B_ * S_ * HID_];
__device__ bf16  g_cl [(size_t)B_ * S_ * HID_];

// ---------------- helpers ----------------
__device__ __forceinline__ void cp16(void* dst, const void* src) {
    unsigned d = (unsigned)__cvta_generic_to_shared(dst);
    asm volatile("cp.async.cg.shared.global [%0], [%1], 16;\n" :: "r"(d), "l"(src));
}
__device__ __forceinline__ void cp_commit() { asm volatile("cp.async.commit_group;\n"); }
__device__ __forceinline__ void cp_wait0()  { asm volatile("cp.async.wait_group 0;\n"); }

__device__ __forceinline__ void ldsm4(uint32_t* r, const void* p) {
    uint32_t a = (uint32_t)__cvta_generic_to_shared(p);
    asm volatile("ldmatrix.sync.aligned.m8n8.x4.shared.b16 {%0,%1,%2,%3}, [%4];\n"
        : "=r"(r[0]), "=r"(r[1]), "=r"(r[2]), "=r"(r[3]) : "r"(a));
}
__device__ __forceinline__ void ldsm4t(uint32_t* r, const void* p) {
    uint32_t a = (uint32_t)__cvta_generic_to_shared(p);
    asm volatile("ldmatrix.sync.aligned.m8n8.x4.trans.shared.b16 {%0,%1,%2,%3}, [%4];\n"
        : "=r"(r[0]), "=r"(r[1]), "=r"(r[2]), "=r"(r[3]) : "r"(a));
}

// m16n8k16 bf16 mma, fp32 accumulate
__device__ __forceinline__ void mma16(float* c, const uint32_t* a, uint32_t b0, uint32_t b1) {
    asm volatile(
        "mma.sync.aligned.m16n8k16.row.col.f32.bf16.bf16.f32 "
        "{%0,%1,%2,%3},{%4,%5,%6,%7},{%8,%9},{%0,%1,%2,%3};\n"
        : "+f"(c[0]), "+f"(c[1]), "+f"(c[2]), "+f"(c[3])
        : "r"(a[0]), "r"(a[1]), "r"(a[2]), "r"(a[3]), "r"(b0), "r"(b1));
}
// 3-product bf16 emulated-fp32 mma
__device__ __forceinline__ void mma16x3(float* c, const uint32_t* ah, const uint32_t* al,
                                        uint32_t bh0, uint32_t bh1, uint32_t bl0, uint32_t bl1) {
    mma16(c, ah, bh0, bh1);
    mma16(c, al, bh0, bh1);
    mma16(c, ah, bl0, bl1);
}

__device__ __forceinline__ uint32_t packh(float e, float o) {
    __nv_bfloat162 t = __floats2bfloat162_rn(e, o);   // .x = e (low half)
    return *reinterpret_cast<const uint32_t*>(&t);
}
__device__ __forceinline__ uint32_t packl(float e, float o) {
    float he = __bfloat162float(__float2bfloat16_rn(e));
    float ho = __bfloat162float(__float2bfloat16_rn(o));
    return packh(e - he, o - ho);
}
__device__ __forceinline__ void sstore(bf16* oh, bf16* ol, int i, float v) {
    bf16 h = __float2bfloat16_rn(v);
    oh[i] = h;
    ol[i] = __float2bfloat16_rn(v - __bfloat162float(h));
}

// ---------------- split pass: fp32 -> bf16 hi + bf16 lo ----------------
__global__ void split_kernel(const float* __restrict__ src,
                             bf16* __restrict__ dh, bf16* __restrict__ dl)
{
    int i = (blockIdx.x * blockDim.x + threadIdx.x) * 4;
    float4 x = *(const float4*)(src + i);
    uint32_t h01 = packh(x.x, x.y), h23 = packh(x.z, x.w);
    uint32_t l01 = packl(x.x, x.y), l23 = packl(x.z, x.w);
    *(uint32_t*)(dh + i)     = h01;
    *(uint32_t*)(dh + i + 2) = h23;
    *(uint32_t*)(dl + i)     = l01;
    *(uint32_t*)(dl + i + 2) = l23;
}

// ---------------- NT GEMM: C[m,n] = sum_k A[m,k]*W[n,k], bf16x3 ----------------
#define GBM 128
#define GBN 256
#define GBK 32
#define ARS 40   // smem row stride (halves): 32 + 8 pad (80B, conflict-free ldsm)

__global__ __launch_bounds__(256, 1) void gemm_bf3(
    const bf16* __restrict__ Ah, const bf16* __restrict__ Al,
    const bf16* __restrict__ Wh, const bf16* __restrict__ Wl,
    const float* __restrict__ bias, float* __restrict__ C,
    int N, int K, int mode)
{
    extern __shared__ char smraw[];
    bf16* sAh = (bf16*)smraw;               // [2][128][40]
    bf16* sAl = sAh + 2 * GBM * ARS;
    bf16* sBh = sAl + 2 * GBM * ARS;        // [2][256][40]
    bf16* sBl = sBh + 2 * GBN * ARS;

    int tid = threadIdx.x, lane = tid & 31, wid = tid >> 5;
    int g = lane >> 2, tg = lane & 3;
    int wm = (wid & 1) << 6, wn = (wid >> 1) << 6;
    int m0 = blockIdx.y * GBM, n0 = blockIdx.x * GBN;
    const bf16* Abh = Ah + (size_t)m0 * K;
    const bf16* Abl = Al + (size_t)m0 * K;
    const bf16* Bbh = Wh + (size_t)n0 * K;
    const bf16* Bbl = Wl + (size_t)n0 * K;

    float acc[4][8][4];
#pragma unroll
    for (int i = 0; i < 4; i++)
#pragma unroll
        for (int j = 0; j < 8; j++)
#pragma unroll
            for (int c = 0; c < 4; c++) acc[i][j][c] = 0.f;

    int nk = K / GBK;

    auto load_tile = [&](int kt, int buf) {
        int k0 = kt * GBK;
        bf16* ah = sAh + buf * GBM * ARS;
        bf16* al = sAl + buf * GBM * ARS;
        bf16* bh = sBh + buf * GBN * ARS;
        bf16* bl = sBl + buf * GBN * ARS;
#pragma unroll
        for (int i = 0; i < 2; i++) {               // A: 128 rows x 4 chunks
            int idx = tid + i * 256;
            int row = idx >> 2, q = idx & 3;
            size_t go = (size_t)row * K + k0 + q * 8;
            cp16(&ah[row * ARS + q * 8], Abh + go);
            cp16(&al[row * ARS + q * 8], Abl + go);
        }
#pragma unroll
        for (int i = 0; i < 4; i++) {               // B: 256 rows x 4 chunks
            int idx = tid + i * 256;
            int row = idx >> 2, q = idx & 3;
            size_t go = (size_t)row * K + k0 + q * 8;
            cp16(&bh[row * ARS + q * 8], Bbh + go);
            cp16(&bl[row * ARS + q * 8], Bbl + go);
        }
    };

    load_tile(0, 0);
    cp_commit();

    for (int kt = 0; kt < nk; kt++) {
        cp_wait0();
        __syncthreads();
        int buf = kt & 1;
        if (kt + 1 < nk) { load_tile(kt + 1, buf ^ 1); cp_commit(); }

        const bf16* ah = sAh + buf * GBM * ARS;
        const bf16* al = sAl + buf * GBM * ARS;
        const bf16* bh = sBh + buf * GBN * ARS;
        const bf16* bl = sBl + buf * GBN * ARS;

#pragma unroll
        for (int k16 = 0; k16 < 2; k16++) {
            int kk = k16 * 16 + (lane >> 4) * 8;
            uint32_t fah[4][4], fal[4][4];
#pragma unroll
            for (int mi = 0; mi < 4; mi++) {
                int aoff = (wm + mi * 16 + (lane & 15)) * ARS + kk;
                ldsm4(fah[mi], ah + aoff);
                ldsm4(fal[mi], al + aoff);
            }
#pragma unroll
            for (int njp = 0; njp < 4; njp++) {
                int boff = (wn + njp * 16 + (lane & 15)) * ARS + kk;
                uint32_t fbh[4], fbl[4];
                ldsm4(fbh, bh + boff);
                ldsm4(fbl, bl + boff);
#pragma unroll
                for (int mi = 0; mi < 4; mi++) {
                    mma16x3(acc[mi][2 * njp],     fah[mi], fal[mi], fbh[0], fbh[2], fbl[0], fbl[2]);
                    mma16x3(acc[mi][2 * njp + 1], fah[mi], fal[mi], fbh[1], fbh[3], fbl[1], fbl[3]);
                }
            }
        }
    }

    // epilogue
#pragma unroll
    for (int mi = 0; mi < 4; mi++) {
#pragma unroll
        for (int nj = 0; nj < 8; nj++) {
            int col = n0 + wn + nj * 8 + tg * 2;
#pragma unroll
            for (int half = 0; half < 2; half++) {
                int row = m0 + wm + mi * 16 + g + half * 8;
                float v0 = acc[mi][nj][half * 2], v1 = acc[mi][nj][half * 2 + 1];
                if (mode == 0) {
                    C[(size_t)row * N + col]     = v0 + bias[col];
                    C[(size_t)row * N + col + 1] = v1 + bias[col + 1];
                } else {
                    int bb = row >> 11, s = row & (S_ - 1);
                    if (col < HID_) {
                        int hh = col >> 7, d = col & 127;
                        size_t o = (((size_t)bb * NH_ + hh) * S_ + s) * HD_ + d;
                        g_qf[o] = v0; g_qf[o + 1] = v1;
                    } else {
                        int n2 = col - HID_;
                        int kh = n2 >> 8, cc = n2 & 255;
                        if (cc < 128) {
                            size_t o = (((size_t)bb * NKV_ + kh) * S_ + s) * HD_ + cc;
                            g_kf[o] = v0; g_kf[o + 1] = v1;
                        } else {
                            int d = cc - 128;
                            size_t o = (((size_t)bb * NKV_ + kh) * S_ + s) * HD_ + d;
                            *(uint32_t*)(g_vh + o) = packh(v0, v1);
                            *(uint32_t*)(g_vl + o) = packl(v0, v1);
                        }
                    }
                }
            }
        }
    }
}

// ---------------- RoPE + split (g_qf/g_kf fp32 -> hi/lo bf16) ----------------
__global__ void rope_split(const float* __restrict__ cosT, const float* __restrict__ sinT)
{
    int idx = blockIdx.x * blockDim.x + threadIdx.x;
    int d = idx & 63;
    int r = idx >> 6;
    int s = r & (S_ - 1);
    int hh = r >> 11;
    float c1 = cosT[s * HD_ + d],      s1 = sinT[s * HD_ + d];
    float c2 = cosT[s * HD_ + d + 64], s2 = sinT[s * HD_ + d + 64];
    const float* p;
    bf16 *oh, *ol;
    if (hh < B_ * NH_) {
        p  = g_qf + (size_t)r * HD_;
        oh = g_qh + (size_t)r * HD_;
        ol = g_ql + (size_t)r * HD_;
    } else {
        size_t rr = (size_t)r - (size_t)B_ * NH_ * S_;
        p  = g_kf + rr * HD_;
        oh = g_kh + rr * HD_;
        ol = g_kl + rr * HD_;
    }
    float x1 = p[d], x2 = p[d + 64];
    sstore(oh, ol, d,      x1 * c1 - x2 * s1);
    sstore(oh, ol, d + 64, x2 * c2 + x1 * s2);
}

// ---------------- Flash attention (causal, GQA), bf16x3 ----------------
#define AQ 128
#define AK 64
#define RS_ 136   // halves: 128 + 8 pad (272B rows, 16B-aligned, ldsm conflict-free)

__global__ __launch_bounds__(256, 1) void attn_bf3()
{
    extern __shared__ char smraw[];
    bf16* Qh = (bf16*)smraw;          // [128][136]
    bf16* Ql = Qh + AQ * RS_;
    bf16* Kh = Ql + AQ * RS_;         // [64][136]
    bf16* Kl = Kh + AK * RS_;
    bf16* Vh = Kl + AK * RS_;         // [64][136]
    bf16* Vl = Vh + AK * RS_;

    int qt = blockIdx.x, h = blockIdx.y, b = blockIdx.z;
    int tid = threadIdx.x, lane = tid & 31, wid = tid >> 5;
    int g = lane >> 2, tg = lane & 3;

    const bf16* Qbh = g_qh + (((size_t)b * NH_ + h) * S_ + (size_t)qt * AQ) * HD_;
    const bf16* Qbl = g_ql + (((size_t)b * NH_ + h) * S_ + (size_t)qt * AQ) * HD_;
    const bf16* Kbh = g_kh + ((size_t)b * NKV_ + (h >> 2)) * S_ * HD_;
    const bf16* Kbl = g_kl + ((size_t)b * NKV_ + (h >> 2)) * S_ * HD_;
    const bf16* Vbh = g_vh + ((size_t)b * NKV_ + (h >> 2)) * S_ * HD_;
    const bf16* Vbl = g_vl + ((size_t)b * NKV_ + (h >> 2)) * S_ * HD_;

#pragma unroll
    for (int i = 0; i < 8; i++) {
        int idx = tid + i * 256;
        int row = idx >> 4, q = idx & 15;
        size_t go = (size_t)row * HD_ + q * 8;
        cp16(&Qh[row * RS_ + q * 8], Qbh + go);
        cp16(&Ql[row * RS_ + q * 8], Qbl + go);
    }
    cp_commit();

    float o[16][4];
#pragma unroll
    for (int j = 0; j < 16; j++)
#pragma unroll
        for (int c = 0; c < 4; c++) o[j][c] = 0.f;
    float m0 = -1e30f, m1 = -1e30f, l0 = 0.f, l1 = 0.f;
    const float scale = 0.08838834764831845f;
    int pr = wid * 16;

    int nkt = (qt + 1) * 2;
    for (int kt = 0; kt < nkt; kt++) {
        __syncthreads();
#pragma unroll
        for (int i = 0; i < 4; i++) {
            int idx = tid + i * 256;
            int row = idx >> 4, q = idx & 15;
            size_t go = (size_t)(kt * AK + row) * HD_ + q * 8;
            cp16(&Kh[row * RS_ + q * 8], Kbh + go);
            cp16(&Kl[row * RS_ + q * 8], Kbl + go);
            cp16(&Vh[row * RS_ + q * 8], Vbh + go);
            cp16(&Vl[row * RS_ + q * 8], Vbl + go);
        }
        cp_commit();
        cp_wait0();
        __syncthreads();

        // S = Q K^T
        float sf[8][4];
#pragma unroll
        for (int j = 0; j < 8; j++)
#pragma unroll
            for (int c = 0; c < 4; c++) sf[j][c] = 0.f;

#pragma unroll
        for (int k16 = 0; k16 < 8; k16++) {
            int kk = k16 * 16 + (lane >> 4) * 8;
            int aoff = (pr + (lane & 15)) * RS_ + kk;
            uint32_t fah[4], fal[4];
            ldsm4(fah, Qh + aoff);
            ldsm4(fal, Ql + aoff);
#pragma unroll
            for (int njp = 0; njp < 4; njp++) {
                int boff = (njp * 16 + (lane & 15)) * RS_ + kk;
                uint32_t fbh[4], fbl[4];
                ldsm4(fbh, Kh + boff);
                ldsm4(fbl, Kl + boff);
                mma16x3(sf[2 * njp],     fah, fal, fbh[0], fbh[2], fbl[0], fbl[2]);
                mma16x3(sf[2 * njp + 1], fah, fal, fbh[1], fbh[3], fbl[1], fbl[3]);
            }
        }

        // scale + causal mask + online softmax
        int row0 = qt * AQ + wid * 16 + g;
        int colb = kt * AK + tg * 2;
        float mx0 = -1e30f, mx1 = -1e30f;
#pragma unroll
        for (int nj = 0; nj < 8; nj++) {
#pragma unroll
            for (int c = 0; c < 4; c++) {
                int col = colb + nj * 8 + (c & 1);
                int row = row0 + ((c & 2) ? 8 : 0);
                float v = sf[nj][c] * scale;
                if (col > row) v = -1e30f;
                sf[nj][c] = v;
                if (c < 2) mx0 = fmaxf(mx0, v); else mx1 = fmaxf(mx1, v);
            }
        }
        mx0 = fmaxf(mx0, __shfl_xor_sync(0xffffffffu, mx0, 1));
        mx0 = fmaxf(mx0, __shfl_xor_sync(0xffffffffu, mx0, 2));
        mx1 = fmaxf(mx1, __shfl_xor_sync(0xffffffffu, mx1, 1));
        mx1 = fmaxf(mx1, __shfl_xor_sync(0xffffffffu, mx1, 2));

        float mn0 = fmaxf(m0, mx0), mn1 = fmaxf(m1, mx1);
        float al0 = __expf(m0 - mn0), al1 = __expf(m1 - mn1);
        m0 = mn0; m1 = mn1;

        float rs0 = 0.f, rs1 = 0.f;
#pragma unroll
        for (int nj = 0; nj < 8; nj++) {
            float p0 = __expf(sf[nj][0] - mn0), p1 = __expf(sf[nj][1] - mn0);
            float p2 = __expf(sf[nj][2] - mn1), p3 = __expf(sf[nj][3] - mn1);
            sf[nj][0] = p0; sf[nj][1] = p1; sf[nj][2] = p2; sf[nj][3] = p3;
            rs0 += p0 + p1; rs1 += p2 + p3;
        }
        rs0 += __shfl_xor_sync(0xffffffffu, rs0, 1);
        rs0 += __shfl_xor_sync(0xffffffffu, rs0, 2);
        rs1 += __shfl_xor_sync(0xffffffffu, rs1, 1);
        rs1 += __shfl_xor_sync(0xffffffffu, rs1, 2);
        l0 = l0 * al0 + rs0;
        l1 = l1 * al1 + rs1;
#pragma unroll
        for (int j = 0; j < 16; j++) {
            o[j][0] *= al0; o[j][1] *= al0; o[j][2] *= al1; o[j][3] *= al1;
        }

        // O += P @ V  (P fragments packed in registers, V via ldmatrix.trans)
#pragma unroll
        for (int t = 0; t < 4; t++) {
            uint32_t pah[4], pal[4];
            pah[0] = packh(sf[2 * t][0], sf[2 * t][1]);
            pal[0] = packl(sf[2 * t][0], sf[2 * t][1]);
            pah[1] = packh(sf[2 * t][2], sf[2 * t][3]);
            pal[1] = packl(sf[2 * t][2], sf[2 * t][3]);
            pah[2] = packh(sf[2 * t + 1][0], sf[2 * t + 1][1]);
            pal[2] = packl(sf[2 * t + 1][0], sf[2 * t + 1][1]);
            pah[3] = packh(sf[2 * t + 1][2], sf[2 * t + 1][3]);
            pal[3] = packl(sf[2 * t + 1][2], sf[2 * t + 1][3]);
#pragma unroll
            for (int dj = 0; dj < 8; dj++) {
                int voff = (t * 16 + (lane & 15)) * RS_ + dj * 16 + (lane >> 4) * 8;
                uint32_t fvh[4], fvl[4];
                ldsm4t(fvh, Vh + voff);
                ldsm4t(fvl, Vl + voff);
                mma16x3(o[2 * dj],     pah, pal, fvh[0], fvh[1], fvl[0], fvl[1]);
                mma16x3(o[2 * dj + 1], pah, pal, fvh[2], fvh[3], fvl[2], fvl[3]);
            }
        }
    }

    // epilogue: O/l -> split ctx (bf16 hi/lo)
    float il0 = 1.f / l0, il1 = 1.f / l1;
    int row0 = qt * AQ + wid * 16 + g;
    size_t b0 = ((size_t)b * S_ + row0) * HID_ + (size_t)h * HD_;
    size_t b1 = b0 + (size_t)8 * HID_;
#pragma unroll
    for (int nj = 0; nj < 16; nj++) {
        int d = nj * 8 + tg * 2;
        float v0 = o[nj][0] * il0, v1 = o[nj][1] * il0;
        *(uint32_t*)(g_ch + b0 + d) = packh(v0, v1);
        *(uint32_t*)(g_cl + b0 + d) = packl(v0, v1);
        float w0 = o[nj][2] * il1, w1 = o[nj][3] * il1;
        *(uint32_t*)(g_ch + b1 + d) = packh(w0, w1);
        *(uint32_t*)(g_cl + b1 + d) = packl(w0, w1);
    }
}

// ---------------- launch ----------------
extern "C" void kernel_launch(void* const* d_in, const int* in_sizes, int n_in,
                              void* d_out, int out_size)
{
    const float* hs   = (const float*)d_in[0];
    const float* cosT = (const float*)d_in[2];
    const float* sinT = (const float*)d_in[3];
    const float* Wq   = (const float*)d_in[4];
    const float* Wkv  = (const float*)d_in[5];
    const float* Wd   = (const float*)d_in[6];
    const float* bd   = (const float*)d_in[7];
    float* out = (float*)d_out;

    cudaFuncSetAttribute(gemm_bf3, cudaFuncAttributeMaxDynamicSharedMemorySize, 122880);
    cudaFuncSetAttribute(attn_bf3, cudaFuncAttributeMaxDynamicSharedMemorySize, 139264);

    void *hsh, *hsl, *wh, *wl, *wdh, *wdl, *ch, *cl;
    cudaGetSymbolAddress(&hsh, g_hsh);  cudaGetSymbolAddress(&hsl, g_hsl);
    cudaGetSymbolAddress(&wh,  g_wh);   cudaGetSymbolAddress(&wl,  g_wl);
    cudaGetSymbolAddress(&wdh, g_wdh);  cudaGetSymbolAddress(&wdl, g_wdl);
    cudaGetSymbolAddress(&ch,  g_ch);   cudaGetSymbolAddress(&cl,  g_cl);

    const int nhs = B_ * S_ * HID_;            // 16.8M
    const int nwq = HID_ * HID_;               // 16.8M
    const int nwkv = 2 * NKV_ * HD_ * HID_;    // 8.4M

    // 0) split inputs into bf16 hi/lo
    split_kernel<<<nhs / 1024, 256>>>(hs, (bf16*)hsh, (bf16*)hsl);
    split_kernel<<<nwq / 1024, 256>>>(Wq, (bf16*)wh, (bf16*)wl);
    split_kernel<<<nwkv / 1024, 256>>>(Wkv, (bf16*)wh + nwq, (bf16*)wl + nwq);
    split_kernel<<<nwq / 1024, 256>>>(Wd, (bf16*)wdh, (bf16*)wdl);

    // 1) fused QKV projection (scatter epilogue: q,k fp32; v split bf16)
    gemm_bf3<<<dim3((HID_ + 2 * NKV_ * HD_) / GBN, (B_ * S_) / GBM), 256, 122880>>>(
        (const bf16*)hsh, (const bf16*)hsl, (const bf16*)wh, (const bf16*)wl,
        bd, out, HID_ + 2 * NKV_ * HD_, HID_, 1);

    // 2) RoPE + split q,k
    rope_split<<<(B_ * (NH_ + NKV_) * S_ * 64) / 256, 256>>>(cosT, sinT);

    // 3) causal flash attention -> split ctx
    attn_bf3<<<dim3(S_ / AQ, NH_, B_), 256, 139264>>>();

    // 4) output projection + bias
    gemm_bf3<<<dim3(HID_ / GBN, (B_ * S_) / GBM), 256, 122880>>>(
        (const bf16*)ch, (const bf16*)cl, (const bf16*)wdh, (const bf16*)wdl,
        bd, out, HID_, HID_, 0);
}

// round 5
// speedup vs baseline: 1.7243x; 1.0199x over previous
#include <cuda_runtime.h>
#include <cuda_bf16.h>
#include <cstdint>

#define B_   2
#define S_   2048
#define HID_ 4096
#define NH_  32
#define NKV_ 8
#define HD_  128

typedef __nv_bfloat16 bf16;

// ---------------- device scratch (no cudaMalloc allowed) ----------------
__device__ bf16  g_hsh[(size_t)B_ * S_ * HID_];
__device__ bf16  g_hsl[(size_t)B_ * S_ * HID_];
__device__ bf16  g_wh [(size_t)(HID_ + 2 * NKV_ * HD_) * HID_];
__device__ bf16  g_wl [(size_t)(HID_ + 2 * NKV_ * HD_) * HID_];
__device__ bf16  g_wdh[(size_t)HID_ * HID_];
__device__ bf16  g_wdl[(size_t)HID_ * HID_];
__device__ float g_qf [(size_t)B_ * NH_ * S_ * HD_];
__device__ float g_kf [(size_t)B_ * NKV_ * S_ * HD_];
__device__ bf16  g_qh [(size_t)B_ * NH_ * S_ * HD_];
__device__ bf16  g_ql [(size_t)B_ * NH_ * S_ * HD_];
__device__ bf16  g_kh [(size_t)B_ * NKV_ * S_ * HD_];
__device__ bf16  g_kl [(size_t)B_ * NKV_ * S_ * HD_];
__device__ bf16  g_vh [(size_t)B_ * NKV_ * S_ * HD_];
__device__ bf16  g_vl [(size_t)B_ * NKV_ * S_ * HD_];
__device__ bf16  g_ch [(size_t)B_ * S_ * HID_];
__device__ bf16  g_cl [(size_t)B_ * S_ * HID_];

// ---------------- helpers ----------------
__device__ __forceinline__ void cp16(void* dst, const void* src) {
    unsigned d = (unsigned)__cvta_generic_to_shared(dst);
    asm volatile("cp.async.cg.shared.global [%0], [%1], 16;\n" :: "r"(d), "l"(src));
}
__device__ __forceinline__ void cp_commit() { asm volatile("cp.async.commit_group;\n"); }
__device__ __forceinline__ void cp_wait0()  { asm volatile("cp.async.wait_group 0;\n"); }
__device__ __forceinline__ void cp_wait1()  { asm volatile("cp.async.wait_group 1;\n"); }

__device__ __forceinline__ void ldsm4(uint32_t* r, const void* p) {
    uint32_t a = (uint32_t)__cvta_generic_to_shared(p);
    asm volatile("ldmatrix.sync.aligned.m8n8.x4.shared.b16 {%0,%1,%2,%3}, [%4];\n"
        : "=r"(r[0]), "=r"(r[1]), "=r"(r[2]), "=r"(r[3]) : "r"(a));
}
__device__ __forceinline__ void ldsm4t(uint32_t* r, const void* p) {
    uint32_t a = (uint32_t)__cvta_generic_to_shared(p);
    asm volatile("ldmatrix.sync.aligned.m8n8.x4.trans.shared.b16 {%0,%1,%2,%3}, [%4];\n"
        : "=r"(r[0]), "=r"(r[1]), "=r"(r[2]), "=r"(r[3]) : "r"(a));
}

// m16n8k16 bf16 mma, fp32 accumulate
__device__ __forceinline__ void mma16(float* c, const uint32_t* a, uint32_t b0, uint32_t b1) {
    asm volatile(
        "mma.sync.aligned.m16n8k16.row.col.f32.bf16.bf16.f32 "
        "{%0,%1,%2,%3},{%4,%5,%6,%7},{%8,%9},{%0,%1,%2,%3};\n"
        : "+f"(c[0]), "+f"(c[1]), "+f"(c[2]), "+f"(c[3])
        : "r"(a[0]), "r"(a[1]), "r"(a[2]), "r"(a[3]), "r"(b0), "r"(b1));
}
// 3-product bf16 emulated-fp32 mma
__device__ __forceinline__ void mma16x3(float* c, const uint32_t* ah, const uint32_t* al,
                                        uint32_t bh0, uint32_t bh1, uint32_t bl0, uint32_t bl1) {
    mma16(c, ah, bh0, bh1);
    mma16(c, al, bh0, bh1);
    mma16(c, ah, bl0, bl1);
}

__device__ __forceinline__ uint32_t packh(float e, float o) {
    __nv_bfloat162 t = __floats2bfloat162_rn(e, o);
    return *reinterpret_cast<const uint32_t*>(&t);
}
__device__ __forceinline__ uint32_t packl(float e, float o) {
    float he = __bfloat162float(__float2bfloat16_rn(e));
    float ho = __bfloat162float(__float2bfloat16_rn(o));
    return packh(e - he, o - ho);
}
__device__ __forceinline__ void sstore(bf16* oh, bf16* ol, int i, float v) {
    bf16 h = __float2bfloat16_rn(v);
    oh[i] = h;
    ol[i] = __float2bfloat16_rn(v - __bfloat162float(h));
}

// ---------------- split pass: fp32 -> bf16 hi + bf16 lo ----------------
__global__ void split_kernel(const float* __restrict__ src,
                             bf16* __restrict__ dh, bf16* __restrict__ dl)
{
    int i = (blockIdx.x * blockDim.x + threadIdx.x) * 4;
    float4 x = *(const float4*)(src + i);
    *(uint32_t*)(dh + i)     = packh(x.x, x.y);
    *(uint32_t*)(dh + i + 2) = packh(x.z, x.w);
    *(uint32_t*)(dl + i)     = packl(x.x, x.y);
    *(uint32_t*)(dl + i + 2) = packl(x.z, x.w);
}

// ---------------- NT GEMM: C[m,n] = sum_k A[m,k]*W[n,k], bf16x3, 3-stage ------
#define GBM 128
#define GBN 256
#define GBK 32
#define ARS 40                 // smem row stride (halves)
#define NSTG 3
#define AH_STG (GBM * ARS)     // 5120 halves
#define STGH ((2 * GBM + 2 * GBN) * ARS)   // 30720 halves per stage
#define GSMEM (NSTG * STGH * 2)            // 184320 bytes

__global__ __launch_bounds__(256, 1) void gemm_bf3(
    const bf16* __restrict__ Ah, const bf16* __restrict__ Al,
    const bf16* __restrict__ Wh, const bf16* __restrict__ Wl,
    const float* __restrict__ bias, float* __restrict__ C,
    int N, int K, int mode)
{
    extern __shared__ bf16 smh[];

    int tid = threadIdx.x, lane = tid & 31, wid = tid >> 5;
    int g = lane >> 2, tg = lane & 3;
    int wm = (wid & 1) << 6, wn = (wid >> 1) << 6;
    int m0 = blockIdx.y * GBM, n0 = blockIdx.x * GBN;
    const bf16* Abh = Ah + (size_t)m0 * K;
    const bf16* Abl = Al + (size_t)m0 * K;
    const bf16* Bbh = Wh + (size_t)n0 * K;
    const bf16* Bbl = Wl + (size_t)n0 * K;

    float acc[4][8][4];
#pragma unroll
    for (int i = 0; i < 4; i++)
#pragma unroll
        for (int j = 0; j < 8; j++)
#pragma unroll
            for (int c = 0; c < 4; c++) acc[i][j][c] = 0.f;

    int nk = K / GBK;

    auto load_tile = [&](int kt, int s) {
        int k0 = kt * GBK;
        bf16* ah = smh + s * STGH;
        bf16* al = ah + AH_STG;
        bf16* bh = al + AH_STG;
        bf16* bl = bh + GBN * ARS;
#pragma unroll
        for (int i = 0; i < 2; i++) {
            int idx = tid + i * 256;
            int row = idx >> 2, q = idx & 3;
            size_t go = (size_t)row * K + k0 + q * 8;
            cp16(&ah[row * ARS + q * 8], Abh + go);
            cp16(&al[row * ARS + q * 8], Abl + go);
        }
#pragma unroll
        for (int i = 0; i < 4; i++) {
            int idx = tid + i * 256;
            int row = idx >> 2, q = idx & 3;
            size_t go = (size_t)row * K + k0 + q * 8;
            cp16(&bh[row * ARS + q * 8], Bbh + go);
            cp16(&bl[row * ARS + q * 8], Bbl + go);
        }
    };

    load_tile(0, 0); cp_commit();
    load_tile(1, 1); cp_commit();

    for (int kt = 0; kt < nk; kt++) {
        if (kt == nk - 1) cp_wait0(); else cp_wait1();
        __syncthreads();
        if (kt + 2 < nk) { load_tile(kt + 2, (kt + 2) % NSTG); cp_commit(); }

        int s = kt % NSTG;
        const bf16* ah = smh + s * STGH;
        const bf16* al = ah + AH_STG;
        const bf16* bh = al + AH_STG;
        const bf16* bl = bh + GBN * ARS;

#pragma unroll
        for (int k16 = 0; k16 < 2; k16++) {
            int kk = k16 * 16 + (lane >> 4) * 8;
            uint32_t fah[4][4], fal[4][4];
#pragma unroll
            for (int mi = 0; mi < 4; mi++) {
                int aoff = (wm + mi * 16 + (lane & 15)) * ARS + kk;
                ldsm4(fah[mi], ah + aoff);
                ldsm4(fal[mi], al + aoff);
            }
#pragma unroll
            for (int njp = 0; njp < 4; njp++) {
                int boff = (wn + njp * 16 + (lane & 15)) * ARS + kk;
                uint32_t fbh[4], fbl[4];
                ldsm4(fbh, bh + boff);
                ldsm4(fbl, bl + boff);
#pragma unroll
                for (int mi = 0; mi < 4; mi++) {
                    mma16x3(acc[mi][2 * njp],     fah[mi], fal[mi], fbh[0], fbh[2], fbl[0], fbl[2]);
                    mma16x3(acc[mi][2 * njp + 1], fah[mi], fal[mi], fbh[1], fbh[3], fbl[1], fbl[3]);
                }
            }
        }
    }

    // epilogue
#pragma unroll
    for (int mi = 0; mi < 4; mi++) {
#pragma unroll
        for (int nj = 0; nj < 8; nj++) {
            int col = n0 + wn + nj * 8 + tg * 2;
#pragma unroll
            for (int half = 0; half < 2; half++) {
                int row = m0 + wm + mi * 16 + g + half * 8;
                float v0 = acc[mi][nj][half * 2], v1 = acc[mi][nj][half * 2 + 1];
                if (mode == 0) {
                    C[(size_t)row * N + col]     = v0 + bias[col];
                    C[(size_t)row * N + col + 1] = v1 + bias[col + 1];
                } else {
                    int bb = row >> 11, s2 = row & (S_ - 1);
                    if (col < HID_) {
                        int hh = col >> 7, d = col & 127;
                        size_t o = (((size_t)bb * NH_ + hh) * S_ + s2) * HD_ + d;
                        g_qf[o] = v0; g_qf[o + 1] = v1;
                    } else {
                        int n2 = col - HID_;
                        int kh = n2 >> 8, cc = n2 & 255;
                        if (cc < 128) {
                            size_t o = (((size_t)bb * NKV_ + kh) * S_ + s2) * HD_ + cc;
                            g_kf[o] = v0; g_kf[o + 1] = v1;
                        } else {
                            int d = cc - 128;
                            size_t o = (((size_t)bb * NKV_ + kh) * S_ + s2) * HD_ + d;
                            *(uint32_t*)(g_vh + o) = packh(v0, v1);
                            *(uint32_t*)(g_vl + o) = packl(v0, v1);
                        }
                    }
                }
            }
        }
    }
}

// ---------------- RoPE + split (g_qf/g_kf fp32 -> hi/lo bf16) ----------------
__global__ void rope_split(const float* __restrict__ cosT, const float* __restrict__ sinT)
{
    int idx = blockIdx.x * blockDim.x + threadIdx.x;
    int d = idx & 63;
    int r = idx >> 6;
    int s = r & (S_ - 1);
    int hh = r >> 11;
    float c1 = cosT[s * HD_ + d],      s1 = sinT[s * HD_ + d];
    float c2 = cosT[s * HD_ + d + 64], s2 = sinT[s * HD_ + d + 64];
    const float* p;
    bf16 *oh, *ol;
    if (hh < B_ * NH_) {
        p  = g_qf + (size_t)r * HD_;
        oh = g_qh + (size_t)r * HD_;
        ol = g_ql + (size_t)r * HD_;
    } else {
        size_t rr = (size_t)r - (size_t)B_ * NH_ * S_;
        p  = g_kf + rr * HD_;
        oh = g_kh + rr * HD_;
        ol = g_kl + rr * HD_;
    }
    float x1 = p[d], x2 = p[d + 64];
    sstore(oh, ol, d,      x1 * c1 - x2 * s1);
    sstore(oh, ol, d + 64, x2 * c2 + x1 * s2);
}

// ---------------- Flash attention (causal, GQA), bf16x3, double-buffered KV ---
#define AQ 128
#define AK 64
#define RS_ 136
#define KVT (AK * RS_)          // 8704 halves per tile
#define KVSTG (4 * KVT)         // Kh,Kl,Vh,Vl per stage: 34816 halves
#define QOFF 0
#define SBOFF (2 * AQ * RS_)    // 34816 halves
#define ASMEM ((SBOFF + 2 * KVSTG) * 2)   // 208896 bytes

__global__ __launch_bounds__(256, 1) void attn_bf3()
{
    extern __shared__ bf16 smh[];
    bf16* Qh = smh;
    bf16* Ql = Qh + AQ * RS_;

    int qt = blockIdx.x, h = blockIdx.y, b = blockIdx.z;
    int tid = threadIdx.x, lane = tid & 31, wid = tid >> 5;
    int g = lane >> 2, tg = lane & 3;

    const bf16* Qbh = g_qh + (((size_t)b * NH_ + h) * S_ + (size_t)qt * AQ) * HD_;
    const bf16* Qbl = g_ql + (((size_t)b * NH_ + h) * S_ + (size_t)qt * AQ) * HD_;
    const bf16* Kbh = g_kh + ((size_t)b * NKV_ + (h >> 2)) * S_ * HD_;
    const bf16* Kbl = g_kl + ((size_t)b * NKV_ + (h >> 2)) * S_ * HD_;
    const bf16* Vbh = g_vh + ((size_t)b * NKV_ + (h >> 2)) * S_ * HD_;
    const bf16* Vbl = g_vl + ((size_t)b * NKV_ + (h >> 2)) * S_ * HD_;

    // Q tile (one group)
#pragma unroll
    for (int i = 0; i < 8; i++) {
        int idx = tid + i * 256;
        int row = idx >> 4, q = idx & 15;
        size_t go = (size_t)row * HD_ + q * 8;
        cp16(&Qh[row * RS_ + q * 8], Qbh + go);
        cp16(&Ql[row * RS_ + q * 8], Qbl + go);
    }
    cp_commit();

    auto load_kv = [&](int kt, int s) {
        bf16* base = smh + SBOFF + s * KVSTG;
#pragma unroll
        for (int i = 0; i < 4; i++) {
            int idx = tid + i * 256;
            int row = idx >> 4, q = idx & 15;
            size_t go = (size_t)(kt * AK + row) * HD_ + q * 8;
            int so = row * RS_ + q * 8;
            cp16(&base[so],           Kbh + go);
            cp16(&base[KVT + so],     Kbl + go);
            cp16(&base[2 * KVT + so], Vbh + go);
            cp16(&base[3 * KVT + so], Vbl + go);
        }
    };

    float o[16][4];
#pragma unroll
    for (int j = 0; j < 16; j++)
#pragma unroll
        for (int c = 0; c < 4; c++) o[j][c] = 0.f;
    float m0 = -1e30f, m1 = -1e30f, l0 = 0.f, l1 = 0.f;
    const float scale = 0.08838834764831845f;
    int pr = wid * 16;

    int nkt = (qt + 1) * 2;
    load_kv(0, 0); cp_commit();

    for (int kt = 0; kt < nkt; kt++) {
        cp_wait0();
        __syncthreads();
        if (kt + 1 < nkt) { load_kv(kt + 1, (kt + 1) & 1); cp_commit(); }

        bf16* base = smh + SBOFF + (kt & 1) * KVSTG;
        bf16* Kh = base;
        bf16* Kl = base + KVT;
        bf16* Vh = base + 2 * KVT;
        bf16* Vl = base + 3 * KVT;

        // S = Q K^T
        float sf[8][4];
#pragma unroll
        for (int j = 0; j < 8; j++)
#pragma unroll
            for (int c = 0; c < 4; c++) sf[j][c] = 0.f;

#pragma unroll
        for (int k16 = 0; k16 < 8; k16++) {
            int kk = k16 * 16 + (lane >> 4) * 8;
            int aoff = (pr + (lane & 15)) * RS_ + kk;
            uint32_t fah[4], fal[4];
            ldsm4(fah, Qh + aoff);
            ldsm4(fal, Ql + aoff);
#pragma unroll
            for (int njp = 0; njp < 4; njp++) {
                int boff = (njp * 16 + (lane & 15)) * RS_ + kk;
                uint32_t fbh[4], fbl[4];
                ldsm4(fbh, Kh + boff);
                ldsm4(fbl, Kl + boff);
                mma16x3(sf[2 * njp],     fah, fal, fbh[0], fbh[2], fbl[0], fbl[2]);
                mma16x3(sf[2 * njp + 1], fah, fal, fbh[1], fbh[3], fbl[1], fbl[3]);
            }
        }

        // scale + causal mask + online softmax
        int row0 = qt * AQ + wid * 16 + g;
        int colb = kt * AK + tg * 2;
        float mx0 = -1e30f, mx1 = -1e30f;
#pragma unroll
        for (int nj = 0; nj < 8; nj++) {
#pragma unroll
            for (int c = 0; c < 4; c++) {
                int col = colb + nj * 8 + (c & 1);
                int row = row0 + ((c & 2) ? 8 : 0);
                float v = sf[nj][c] * scale;
                if (col > row) v = -1e30f;
                sf[nj][c] = v;
                if (c < 2) mx0 = fmaxf(mx0, v); else mx1 = fmaxf(mx1, v);
            }
        }
        mx0 = fmaxf(mx0, __shfl_xor_sync(0xffffffffu, mx0, 1));
        mx0 = fmaxf(mx0, __shfl_xor_sync(0xffffffffu, mx0, 2));
        mx1 = fmaxf(mx1, __shfl_xor_sync(0xffffffffu, mx1, 1));
        mx1 = fmaxf(mx1, __shfl_xor_sync(0xffffffffu, mx1, 2));

        float mn0 = fmaxf(m0, mx0), mn1 = fmaxf(m1, mx1);
        float al0 = __expf(m0 - mn0), al1 = __expf(m1 - mn1);
        m0 = mn0; m1 = mn1;

        float rs0 = 0.f, rs1 = 0.f;
#pragma unroll
        for (int nj = 0; nj < 8; nj++) {
            float p0 = __expf(sf[nj][0] - mn0), p1 = __expf(sf[nj][1] - mn0);
            float p2 = __expf(sf[nj][2] - mn1), p3 = __expf(sf[nj][3] - mn1);
            sf[nj][0] = p0; sf[nj][1] = p1; sf[nj][2] = p2; sf[nj][3] = p3;
            rs0 += p0 + p1; rs1 += p2 + p3;
        }
        rs0 += __shfl_xor_sync(0xffffffffu, rs0, 1);
        rs0 += __shfl_xor_sync(0xffffffffu, rs0, 2);
        rs1 += __shfl_xor_sync(0xffffffffu, rs1, 1);
        rs1 += __shfl_xor_sync(0xffffffffu, rs1, 2);
        l0 = l0 * al0 + rs0;
        l1 = l1 * al1 + rs1;
#pragma unroll
        for (int j = 0; j < 16; j++) {
            o[j][0] *= al0; o[j][1] *= al0; o[j][2] *= al1; o[j][3] *= al1;
        }

        // O += P @ V  (P packed in registers, V via ldmatrix.trans)
#pragma unroll
        for (int t = 0; t < 4; t++) {
            uint32_t pah[4], pal[4];
            pah[0] = packh(sf[2 * t][0], sf[2 * t][1]);
            pal[0] = packl(sf[2 * t][0], sf[2 * t][1]);
            pah[1] = packh(sf[2 * t][2], sf[2 * t][3]);
            pal[1] = packl(sf[2 * t][2], sf[2 * t][3]);
            pah[2] = packh(sf[2 * t + 1][0], sf[2 * t + 1][1]);
            pal[2] = packl(sf[2 * t + 1][0], sf[2 * t + 1][1]);
            pah[3] = packh(sf[2 * t + 1][2], sf[2 * t + 1][3]);
            pal[3] = packl(sf[2 * t + 1][2], sf[2 * t + 1][3]);
#pragma unroll
            for (int dj = 0; dj < 8; dj++) {
                int voff = (t * 16 + (lane & 15)) * RS_ + dj * 16 + (lane >> 4) * 8;
                uint32_t fvh[4], fvl[4];
                ldsm4t(fvh, Vh + voff);
                ldsm4t(fvl, Vl + voff);
                mma16x3(o[2 * dj],     pah, pal, fvh[0], fvh[1], fvl[0], fvl[1]);
                mma16x3(o[2 * dj + 1], pah, pal, fvh[2], fvh[3], fvl[2], fvl[3]);
            }
        }
    }

    // epilogue: O/l -> split ctx
    float il0 = 1.f / l0, il1 = 1.f / l1;
    int row0 = qt * AQ + wid * 16 + g;
    size_t b0 = ((size_t)b * S_ + row0) * HID_ + (size_t)h * HD_;
    size_t b1 = b0 + (size_t)8 * HID_;
#pragma unroll
    for (int nj = 0; nj < 16; nj++) {
        int d = nj * 8 + tg * 2;
        float v0 = o[nj][0] * il0, v1 = o[nj][1] * il0;
        *(uint32_t*)(g_ch + b0 + d) = packh(v0, v1);
        *(uint32_t*)(g_cl + b0 + d) = packl(v0, v1);
        float w0 = o[nj][2] * il1, w1 = o[nj][3] * il1;
        *(uint32_t*)(g_ch + b1 + d) = packh(w0, w1);
        *(uint32_t*)(g_cl + b1 + d) = packl(w0, w1);
    }
}

// ---------------- launch ----------------
extern "C" void kernel_launch(void* const* d_in, const int* in_sizes, int n_in,
                              void* d_out, int out_size)
{
    const float* hs   = (const float*)d_in[0];
    const float* cosT = (const float*)d_in[2];
    const float* sinT = (const float*)d_in[3];
    const float* Wq   = (const float*)d_in[4];
    const float* Wkv  = (const float*)d_in[5];
    const float* Wd   = (const float*)d_in[6];
    const float* bd   = (const float*)d_in[7];
    float* out = (float*)d_out;

    cudaFuncSetAttribute(gemm_bf3, cudaFuncAttributeMaxDynamicSharedMemorySize, GSMEM);
    cudaFuncSetAttribute(attn_bf3, cudaFuncAttributeMaxDynamicSharedMemorySize, ASMEM);

    void *hsh, *hsl, *wh, *wl, *wdh, *wdl, *ch, *cl;
    cudaGetSymbolAddress(&hsh, g_hsh);  cudaGetSymbolAddress(&hsl, g_hsl);
    cudaGetSymbolAddress(&wh,  g_wh);   cudaGetSymbolAddress(&wl,  g_wl);
    cudaGetSymbolAddress(&wdh, g_wdh);  cudaGetSymbolAddress(&wdl, g_wdl);
    cudaGetSymbolAddress(&ch,  g_ch);   cudaGetSymbolAddress(&cl,  g_cl);

    const int nhs = B_ * S_ * HID_;
    const int nwq = HID_ * HID_;
    const int nwkv = 2 * NKV_ * HD_ * HID_;

    split_kernel<<<nhs / 1024, 256>>>(hs, (bf16*)hsh, (bf16*)hsl);
    split_kernel<<<nwq / 1024, 256>>>(Wq, (bf16*)wh, (bf16*)wl);
    split_kernel<<<nwkv / 1024, 256>>>(Wkv, (bf16*)wh + nwq, (bf16*)wl + nwq);
    split_kernel<<<nwq / 1024, 256>>>(Wd, (bf16*)wdh, (bf16*)wdl);

    gemm_bf3<<<dim3((HID_ + 2 * NKV_ * HD_) / GBN, (B_ * S_) / GBM), 256, GSMEM>>>(
        (const bf16*)hsh, (const bf16*)hsl, (const bf16*)wh, (const bf16*)wl,
        bd, out, HID_ + 2 * NKV_ * HD_, HID_, 1);

    rope_split<<<(B_ * (NH_ + NKV_) * S_ * 64) / 256, 256>>>(cosT, sinT);

    attn_bf3<<<dim3(S_ / AQ, NH_, B_), 256, ASMEM>>>();

    gemm_bf3<<<dim3(HID_ / GBN, (B_ * S_) / GBM), 256, GSMEM>>>(
        (const bf16*)ch, (const bf16*)cl, (const bf16*)wdh, (const bf16*)wdl,
        bd, out, HID_, HID_, 0);
}

// round 6
// speedup vs baseline: 1.7653x; 1.0237x over previous
#include <cuda_runtime.h>
#include <cuda_bf16.h>
#include <cstdint>

#define B_   2
#define S_   2048
#define HID_ 4096
#define NH_  32
#define NKV_ 8
#define HD_  128

typedef __nv_bfloat16 bf16;

// ---------------- device scratch (no cudaMalloc allowed) ----------------
__device__ bf16  g_hsh[(size_t)B_ * S_ * HID_];
__device__ bf16  g_hsl[(size_t)B_ * S_ * HID_];
__device__ bf16  g_wh [(size_t)(HID_ + 2 * NKV_ * HD_) * HID_];
__device__ bf16  g_wl [(size_t)(HID_ + 2 * NKV_ * HD_) * HID_];
__device__ bf16  g_wdh[(size_t)HID_ * HID_];
__device__ bf16  g_wdl[(size_t)HID_ * HID_];
__device__ float g_qf [(size_t)B_ * NH_ * S_ * HD_];
__device__ float g_kf [(size_t)B_ * NKV_ * S_ * HD_];
__device__ bf16  g_qh [(size_t)B_ * NH_ * S_ * HD_];
__device__ bf16  g_ql [(size_t)B_ * NH_ * S_ * HD_];
__device__ bf16  g_kh [(size_t)B_ * NKV_ * S_ * HD_];
__device__ bf16  g_kl [(size_t)B_ * NKV_ * S_ * HD_];
__device__ bf16  g_vh [(size_t)B_ * NKV_ * S_ * HD_];
__device__ bf16  g_vl [(size_t)B_ * NKV_ * S_ * HD_];
__device__ bf16  g_ch [(size_t)B_ * S_ * HID_];
__device__ bf16  g_cl [(size_t)B_ * S_ * HID_];

// ---------------- helpers ----------------
__device__ __forceinline__ void cp16(void* dst, const void* src) {
    unsigned d = (unsigned)__cvta_generic_to_shared(dst);
    asm volatile("cp.async.cg.shared.global [%0], [%1], 16;\n" :: "r"(d), "l"(src));
}
__device__ __forceinline__ void cp_commit() { asm volatile("cp.async.commit_group;\n"); }
__device__ __forceinline__ void cp_wait0()  { asm volatile("cp.async.wait_group 0;\n"); }
__device__ __forceinline__ void cp_wait1()  { asm volatile("cp.async.wait_group 1;\n"); }

__device__ __forceinline__ void ldsm4(uint32_t* r, const void* p) {
    uint32_t a = (uint32_t)__cvta_generic_to_shared(p);
    asm volatile("ldmatrix.sync.aligned.m8n8.x4.shared.b16 {%0,%1,%2,%3}, [%4];\n"
        : "=r"(r[0]), "=r"(r[1]), "=r"(r[2]), "=r"(r[3]) : "r"(a));
}
__device__ __forceinline__ void ldsm4t(uint32_t* r, const void* p) {
    uint32_t a = (uint32_t)__cvta_generic_to_shared(p);
    asm volatile("ldmatrix.sync.aligned.m8n8.x4.trans.shared.b16 {%0,%1,%2,%3}, [%4];\n"
        : "=r"(r[0]), "=r"(r[1]), "=r"(r[2]), "=r"(r[3]) : "r"(a));
}

// m16n8k16 bf16 mma, fp32 accumulate
__device__ __forceinline__ void mma16(float* c, const uint32_t* a, uint32_t b0, uint32_t b1) {
    asm volatile(
        "mma.sync.aligned.m16n8k16.row.col.f32.bf16.bf16.f32 "
        "{%0,%1,%2,%3},{%4,%5,%6,%7},{%8,%9},{%0,%1,%2,%3};\n"
        : "+f"(c[0]), "+f"(c[1]), "+f"(c[2]), "+f"(c[3])
        : "r"(a[0]), "r"(a[1]), "r"(a[2]), "r"(a[3]), "r"(b0), "r"(b1));
}
// 3-product bf16 emulated-fp32 mma
__device__ __forceinline__ void mma16x3(float* c, const uint32_t* ah, const uint32_t* al,
                                        uint32_t bh0, uint32_t bh1, uint32_t bl0, uint32_t bl1) {
    mma16(c, ah, bh0, bh1);
    mma16(c, al, bh0, bh1);
    mma16(c, ah, bl0, bl1);
}

__device__ __forceinline__ uint32_t packh(float e, float o) {
    __nv_bfloat162 t = __floats2bfloat162_rn(e, o);
    return *reinterpret_cast<const uint32_t*>(&t);
}
__device__ __forceinline__ uint32_t packl(float e, float o) {
    float he = __bfloat162float(__float2bfloat16_rn(e));
    float ho = __bfloat162float(__float2bfloat16_rn(o));
    return packh(e - he, o - ho);
}
__device__ __forceinline__ void sstore(bf16* oh, bf16* ol, int i, float v) {
    bf16 h = __float2bfloat16_rn(v);
    oh[i] = h;
    ol[i] = __float2bfloat16_rn(v - __bfloat162float(h));
}

// ---------------- fused split pass: 4 tensors, fp32 -> bf16 hi + lo ----------
#define NHS_ (B_ * S_ * HID_)
#define NWQ_ (HID_ * HID_)
#define NWKV_ (2 * NKV_ * HD_ * HID_)

__global__ void split4_kernel(const float* __restrict__ hs, const float* __restrict__ Wq,
                              const float* __restrict__ Wkv, const float* __restrict__ Wd)
{
    int t = blockIdx.x * blockDim.x + threadIdx.x;   // one float4 per thread
    const int q0 = NHS_ / 4, q1 = q0 + NWQ_ / 4, q2 = q1 + NWKV_ / 4;
    const float* src;
    bf16 *dh, *dl;
    int i;
    if (t < q0)      { src = hs;  dh = g_hsh; dl = g_hsl; i = t * 4; }
    else if (t < q1) { src = Wq;  dh = g_wh;  dl = g_wl;  i = (t - q0) * 4; }
    else if (t < q2) { src = Wkv; dh = g_wh + NWQ_; dl = g_wl + NWQ_; i = (t - q1) * 4; }
    else             { src = Wd;  dh = g_wdh; dl = g_wdl; i = (t - q2) * 4; }
    float4 x = *(const float4*)(src + i);
    *(uint32_t*)(dh + i)     = packh(x.x, x.y);
    *(uint32_t*)(dh + i + 2) = packh(x.z, x.w);
    *(uint32_t*)(dl + i)     = packl(x.x, x.y);
    *(uint32_t*)(dl + i + 2) = packl(x.z, x.w);
}

// ---------------- NT GEMM: 512 threads, 128x256x32, bf16x3, 3-stage ----------
#define GBM 128
#define GBN 256
#define GBK 32
#define ARS 40                 // smem row stride (halves)
#define NSTG 3
#define AH_STG (GBM * ARS)
#define STGH ((2 * GBM + 2 * GBN) * ARS)   // 30720 halves per stage
#define GSMEM (NSTG * STGH * 2)            // 184320 bytes

__global__ __launch_bounds__(512, 1) void gemm_bf3(
    const bf16* __restrict__ Ah, const bf16* __restrict__ Al,
    const bf16* __restrict__ Wh, const bf16* __restrict__ Wl,
    const float* __restrict__ bias, float* __restrict__ C,
    int N, int K, int mode)
{
    extern __shared__ bf16 smh[];

    int tid = threadIdx.x, lane = tid & 31, wid = tid >> 5;   // wid 0..15
    int g = lane >> 2, tg = lane & 3;
    int wm = (wid & 3) << 5;    // 0,32,64,96
    int wn = (wid >> 2) << 6;   // 0,64,128,192
    int m0 = blockIdx.y * GBM, n0 = blockIdx.x * GBN;
    const bf16* Abh = Ah + (size_t)m0 * K;
    const bf16* Abl = Al + (size_t)m0 * K;
    const bf16* Bbh = Wh + (size_t)n0 * K;
    const bf16* Bbl = Wl + (size_t)n0 * K;

    float acc[2][8][4];
#pragma unroll
    for (int i = 0; i < 2; i++)
#pragma unroll
        for (int j = 0; j < 8; j++)
#pragma unroll
            for (int c = 0; c < 4; c++) acc[i][j][c] = 0.f;

    int nk = K / GBK;

    auto load_tile = [&](int kt, int s) {
        int k0 = kt * GBK;
        bf16* ah = smh + s * STGH;
        bf16* al = ah + AH_STG;
        bf16* bh = al + AH_STG;
        bf16* bl = bh + GBN * ARS;
        {   // A: 512 chunks (row, q), each thread does hi+lo
            int row = tid >> 2, q = tid & 3;
            size_t go = (size_t)row * K + k0 + q * 8;
            cp16(&ah[row * ARS + q * 8], Abh + go);
            cp16(&al[row * ARS + q * 8], Abl + go);
        }
#pragma unroll
        for (int i = 0; i < 2; i++) {   // B: 1024 chunks
            int idx = tid + i * 512;
            int row = idx >> 2, q = idx & 3;
            size_t go = (size_t)row * K + k0 + q * 8;
            cp16(&bh[row * ARS + q * 8], Bbh + go);
            cp16(&bl[row * ARS + q * 8], Bbl + go);
        }
    };

    load_tile(0, 0); cp_commit();
    load_tile(1, 1); cp_commit();

    for (int kt = 0; kt < nk; kt++) {
        if (kt == nk - 1) cp_wait0(); else cp_wait1();
        __syncthreads();
        if (kt + 2 < nk) { load_tile(kt + 2, (kt + 2) % NSTG); cp_commit(); }

        int s = kt % NSTG;
        const bf16* ah = smh + s * STGH;
        const bf16* al = ah + AH_STG;
        const bf16* bh = al + AH_STG;
        const bf16* bl = bh + GBN * ARS;

#pragma unroll
        for (int k16 = 0; k16 < 2; k16++) {
            int kk = k16 * 16 + (lane >> 4) * 8;
            uint32_t fah[2][4], fal[2][4];
#pragma unroll
            for (int mi = 0; mi < 2; mi++) {
                int aoff = (wm + mi * 16 + (lane & 15)) * ARS + kk;
                ldsm4(fah[mi], ah + aoff);
                ldsm4(fal[mi], al + aoff);
            }
#pragma unroll
            for (int njp = 0; njp < 4; njp++) {
                int boff = (wn + njp * 16 + (lane & 15)) * ARS + kk;
                uint32_t fbh[4], fbl[4];
                ldsm4(fbh, bh + boff);
                ldsm4(fbl, bl + boff);
#pragma unroll
                for (int mi = 0; mi < 2; mi++) {
                    mma16x3(acc[mi][2 * njp],     fah[mi], fal[mi], fbh[0], fbh[2], fbl[0], fbl[2]);
                    mma16x3(acc[mi][2 * njp + 1], fah[mi], fal[mi], fbh[1], fbh[3], fbl[1], fbl[3]);
                }
            }
        }
    }

    // epilogue
#pragma unroll
    for (int mi = 0; mi < 2; mi++) {
#pragma unroll
        for (int nj = 0; nj < 8; nj++) {
            int col = n0 + wn + nj * 8 + tg * 2;
#pragma unroll
            for (int half = 0; half < 2; half++) {
                int row = m0 + wm + mi * 16 + g + half * 8;
                float v0 = acc[mi][nj][half * 2], v1 = acc[mi][nj][half * 2 + 1];
                if (mode == 0) {
                    C[(size_t)row * N + col]     = v0 + bias[col];
                    C[(size_t)row * N + col + 1] = v1 + bias[col + 1];
                } else {
                    int bb = row >> 11, s2 = row & (S_ - 1);
                    if (col < HID_) {
                        int hh = col >> 7, d = col & 127;
                        size_t o = (((size_t)bb * NH_ + hh) * S_ + s2) * HD_ + d;
                        g_qf[o] = v0; g_qf[o + 1] = v1;
                    } else {
                        int n2 = col - HID_;
                        int kh = n2 >> 8, cc = n2 & 255;
                        if (cc < 128) {
                            size_t o = (((size_t)bb * NKV_ + kh) * S_ + s2) * HD_ + cc;
                            g_kf[o] = v0; g_kf[o + 1] = v1;
                        } else {
                            int d = cc - 128;
                            size_t o = (((size_t)bb * NKV_ + kh) * S_ + s2) * HD_ + d;
                            *(uint32_t*)(g_vh + o) = packh(v0, v1);
                            *(uint32_t*)(g_vl + o) = packl(v0, v1);
                        }
                    }
                }
            }
        }
    }
}

// ---------------- RoPE + split (g_qf/g_kf fp32 -> hi/lo bf16) ----------------
__global__ void rope_split(const float* __restrict__ cosT, const float* __restrict__ sinT)
{
    int idx = blockIdx.x * blockDim.x + threadIdx.x;
    int d = idx & 63;
    int r = idx >> 6;
    int s = r & (S_ - 1);
    int hh = r >> 11;
    float c1 = cosT[s * HD_ + d],      s1 = sinT[s * HD_ + d];
    float c2 = cosT[s * HD_ + d + 64], s2 = sinT[s * HD_ + d + 64];
    const float* p;
    bf16 *oh, *ol;
    if (hh < B_ * NH_) {
        p  = g_qf + (size_t)r * HD_;
        oh = g_qh + (size_t)r * HD_;
        ol = g_ql + (size_t)r * HD_;
    } else {
        size_t rr = (size_t)r - (size_t)B_ * NH_ * S_;
        p  = g_kf + rr * HD_;
        oh = g_kh + rr * HD_;
        ol = g_kl + rr * HD_;
    }
    float x1 = p[d], x2 = p[d + 64];
    sstore(oh, ol, d,      x1 * c1 - x2 * s1);
    sstore(oh, ol, d + 64, x2 * c2 + x1 * s2);
}

// ---------------- Flash attention (causal, GQA), bf16x3, double-buffered KV ---
#define AQ 128
#define AK 64
#define RS_ 136
#define KVT (AK * RS_)
#define KVSTG (4 * KVT)
#define SBOFF (2 * AQ * RS_)
#define ASMEM ((SBOFF + 2 * KVSTG) * 2)   // 208896 bytes

__global__ __launch_bounds__(256, 1) void attn_bf3()
{
    extern __shared__ bf16 smh[];
    bf16* Qh = smh;
    bf16* Ql = Qh + AQ * RS_;

    int qt = blockIdx.x, h = blockIdx.y, b = blockIdx.z;
    int tid = threadIdx.x, lane = tid & 31, wid = tid >> 5;
    int g = lane >> 2, tg = lane & 3;

    const bf16* Qbh = g_qh + (((size_t)b * NH_ + h) * S_ + (size_t)qt * AQ) * HD_;
    const bf16* Qbl = g_ql + (((size_t)b * NH_ + h) * S_ + (size_t)qt * AQ) * HD_;
    const bf16* Kbh = g_kh + ((size_t)b * NKV_ + (h >> 2)) * S_ * HD_;
    const bf16* Kbl = g_kl + ((size_t)b * NKV_ + (h >> 2)) * S_ * HD_;
    const bf16* Vbh = g_vh + ((size_t)b * NKV_ + (h >> 2)) * S_ * HD_;
    const bf16* Vbl = g_vl + ((size_t)b * NKV_ + (h >> 2)) * S_ * HD_;

#pragma unroll
    for (int i = 0; i < 8; i++) {
        int idx = tid + i * 256;
        int row = idx >> 4, q = idx & 15;
        size_t go = (size_t)row * HD_ + q * 8;
        cp16(&Qh[row * RS_ + q * 8], Qbh + go);
        cp16(&Ql[row * RS_ + q * 8], Qbl + go);
    }
    cp_commit();

    auto load_kv = [&](int kt, int s) {
        bf16* base = smh + SBOFF + s * KVSTG;
#pragma unroll
        for (int i = 0; i < 4; i++) {
            int idx = tid + i * 256;
            int row = idx >> 4, q = idx & 15;
            size_t go = (size_t)(kt * AK + row) * HD_ + q * 8;
            int so = row * RS_ + q * 8;
            cp16(&base[so],           Kbh + go);
            cp16(&base[KVT + so],     Kbl + go);
            cp16(&base[2 * KVT + so], Vbh + go);
            cp16(&base[3 * KVT + so], Vbl + go);
        }
    };

    float o[16][4];
#pragma unroll
    for (int j = 0; j < 16; j++)
#pragma unroll
        for (int c = 0; c < 4; c++) o[j][c] = 0.f;
    float m0 = -1e30f, m1 = -1e30f, l0 = 0.f, l1 = 0.f;
    const float scale = 0.08838834764831845f;
    int pr = wid * 16;

    int nkt = (qt + 1) * 2;
    load_kv(0, 0); cp_commit();

    for (int kt = 0; kt < nkt; kt++) {
        cp_wait0();
        __syncthreads();
        if (kt + 1 < nkt) { load_kv(kt + 1, (kt + 1) & 1); cp_commit(); }

        bf16* base = smh + SBOFF + (kt & 1) * KVSTG;
        bf16* Kh = base;
        bf16* Kl = base + KVT;
        bf16* Vh = base + 2 * KVT;
        bf16* Vl = base + 3 * KVT;

        float sf[8][4];
#pragma unroll
        for (int j = 0; j < 8; j++)
#pragma unroll
            for (int c = 0; c < 4; c++) sf[j][c] = 0.f;

#pragma unroll
        for (int k16 = 0; k16 < 8; k16++) {
            int kk = k16 * 16 + (lane >> 4) * 8;
            int aoff = (pr + (lane & 15)) * RS_ + kk;
            uint32_t fah[4], fal[4];
            ldsm4(fah, Qh + aoff);
            ldsm4(fal, Ql + aoff);
#pragma unroll
            for (int njp = 0; njp < 4; njp++) {
                int boff = (njp * 16 + (lane & 15)) * RS_ + kk;
                uint32_t fbh[4], fbl[4];
                ldsm4(fbh, Kh + boff);
                ldsm4(fbl, Kl + boff);
                mma16x3(sf[2 * njp],     fah, fal, fbh[0], fbh[2], fbl[0], fbl[2]);
                mma16x3(sf[2 * njp + 1], fah, fal, fbh[1], fbh[3], fbl[1], fbl[3]);
            }
        }

        int row0 = qt * AQ + wid * 16 + g;
        int colb = kt * AK + tg * 2;
        float mx0 = -1e30f, mx1 = -1e30f;
#pragma unroll
        for (int nj = 0; nj < 8; nj++) {
#pragma unroll
            for (int c = 0; c < 4; c++) {
                int col = colb + nj * 8 + (c & 1);
                int row = row0 + ((c & 2) ? 8 : 0);
                float v = sf[nj][c] * scale;
                if (col > row) v = -1e30f;
                sf[nj][c] = v;
                if (c < 2) mx0 = fmaxf(mx0, v); else mx1 = fmaxf(mx1, v);
            }
        }
        mx0 = fmaxf(mx0, __shfl_xor_sync(0xffffffffu, mx0, 1));
        mx0 = fmaxf(mx0, __shfl_xor_sync(0xffffffffu, mx0, 2));
        mx1 = fmaxf(mx1, __shfl_xor_sync(0xffffffffu, mx1, 1));
        mx1 = fmaxf(mx1, __shfl_xor_sync(0xffffffffu, mx1, 2));

        float mn0 = fmaxf(m0, mx0), mn1 = fmaxf(m1, mx1);
        float al0 = __expf(m0 - mn0), al1 = __expf(m1 - mn1);
        m0 = mn0; m1 = mn1;

        float rs0 = 0.f, rs1 = 0.f;
#pragma unroll
        for (int nj = 0; nj < 8; nj++) {
            float p0 = __expf(sf[nj][0] - mn0), p1 = __expf(sf[nj][1] - mn0);
            float p2 = __expf(sf[nj][2] - mn1), p3 = __expf(sf[nj][3] - mn1);
            sf[nj][0] = p0; sf[nj][1] = p1; sf[nj][2] = p2; sf[nj][3] = p3;
            rs0 += p0 + p1; rs1 += p2 + p3;
        }
        rs0 += __shfl_xor_sync(0xffffffffu, rs0, 1);
        rs0 += __shfl_xor_sync(0xffffffffu, rs0, 2);
        rs1 += __shfl_xor_sync(0xffffffffu, rs1, 1);
        rs1 += __shfl_xor_sync(0xffffffffu, rs1, 2);
        l0 = l0 * al0 + rs0;
        l1 = l1 * al1 + rs1;
#pragma unroll
        for (int j = 0; j < 16; j++) {
            o[j][0] *= al0; o[j][1] *= al0; o[j][2] *= al1; o[j][3] *= al1;
        }

#pragma unroll
        for (int t = 0; t < 4; t++) {
            uint32_t pah[4], pal[4];
            pah[0] = packh(sf[2 * t][0], sf[2 * t][1]);
            pal[0] = packl(sf[2 * t][0], sf[2 * t][1]);
            pah[1] = packh(sf[2 * t][2], sf[2 * t][3]);
            pal[1] = packl(sf[2 * t][2], sf[2 * t][3]);
            pah[2] = packh(sf[2 * t + 1][0], sf[2 * t + 1][1]);
            pal[2] = packl(sf[2 * t + 1][0], sf[2 * t + 1][1]);
            pah[3] = packh(sf[2 * t + 1][2], sf[2 * t + 1][3]);
            pal[3] = packl(sf[2 * t + 1][2], sf[2 * t + 1][3]);
#pragma unroll
            for (int dj = 0; dj < 8; dj++) {
                int voff = (t * 16 + (lane & 15)) * RS_ + dj * 16 + (lane >> 4) * 8;
                uint32_t fvh[4], fvl[4];
                ldsm4t(fvh, Vh + voff);
                ldsm4t(fvl, Vl + voff);
                mma16x3(o[2 * dj],     pah, pal, fvh[0], fvh[1], fvl[0], fvl[1]);
                mma16x3(o[2 * dj + 1], pah, pal, fvh[2], fvh[3], fvl[2], fvl[3]);
            }
        }
    }

    float il0 = 1.f / l0, il1 = 1.f / l1;
    int row0 = qt * AQ + wid * 16 + g;
    size_t b0 = ((size_t)b * S_ + row0) * HID_ + (size_t)h * HD_;
    size_t b1 = b0 + (size_t)8 * HID_;
#pragma unroll
    for (int nj = 0; nj < 16; nj++) {
        int d = nj * 8 + tg * 2;
        float v0 = o[nj][0] * il0, v1 = o[nj][1] * il0;
        *(uint32_t*)(g_ch + b0 + d) = packh(v0, v1);
        *(uint32_t*)(g_cl + b0 + d) = packl(v0, v1);
        float w0 = o[nj][2] * il1, w1 = o[nj][3] * il1;
        *(uint32_t*)(g_ch + b1 + d) = packh(w0, w1);
        *(uint32_t*)(g_cl + b1 + d) = packl(w0, w1);
    }
}

// ---------------- launch ----------------
extern "C" void kernel_launch(void* const* d_in, const int* in_sizes, int n_in,
                              void* d_out, int out_size)
{
    const float* hs   = (const float*)d_in[0];
    const float* cosT = (const float*)d_in[2];
    const float* sinT = (const float*)d_in[3];
    const float* Wq   = (const float*)d_in[4];
    const float* Wkv  = (const float*)d_in[5];
    const float* Wd   = (const float*)d_in[6];
    const float* bd   = (const float*)d_in[7];
    float* out = (float*)d_out;

    cudaFuncSetAttribute(gemm_bf3, cudaFuncAttributeMaxDynamicSharedMemorySize, GSMEM);
    cudaFuncSetAttribute(attn_bf3, cudaFuncAttributeMaxDynamicSharedMemorySize, ASMEM);

    void *hsh, *hsl, *wh, *wl, *wdh, *wdl, *ch, *cl;
    cudaGetSymbolAddress(&hsh, g_hsh);  cudaGetSymbolAddress(&hsl, g_hsl);
    cudaGetSymbolAddress(&wh,  g_wh);   cudaGetSymbolAddress(&wl,  g_wl);
    cudaGetSymbolAddress(&wdh, g_wdh);  cudaGetSymbolAddress(&wdl, g_wdl);
    cudaGetSymbolAddress(&ch,  g_ch);   cudaGetSymbolAddress(&cl,  g_cl);

    // 0) fused split of all fp32 inputs into bf16 hi/lo
    const int total4 = (NHS_ + NWQ_ + NWKV_ + NWQ_) / 4;   // float4 units
    split4_kernel<<<total4 / 256, 256>>>(hs, Wq, Wkv, Wd);

    // 1) fused QKV projection (scatter epilogue)
    gemm_bf3<<<dim3((HID_ + 2 * NKV_ * HD_) / GBN, (B_ * S_) / GBM), 512, GSMEM>>>(
        (const bf16*)hsh, (const bf16*)hsl, (const bf16*)wh, (const bf16*)wl,
        bd, out, HID_ + 2 * NKV_ * HD_, HID_, 1);

    // 2) RoPE + split q,k
    rope_split<<<(B_ * (NH_ + NKV_) * S_ * 64) / 256, 256>>>(cosT, sinT);

    // 3) causal flash attention -> split ctx
    attn_bf3<<<dim3(S_ / AQ, NH_, B_), 256, ASMEM>>>();

    // 4) output projection + bias
    gemm_bf3<<<dim3(HID_ / GBN, (B_ * S_) / GBM), 512, GSMEM>>>(
        (const bf16*)ch, (const bf16*)cl, (const bf16*)wdh, (const bf16*)wdl,
        bd, out, HID_, HID_, 0);
}